// round 13
// baseline (speedup 1.0000x reference)
#include <cuda_runtime.h>
#include <cstdint>
#include <cstddef>

#define BB 128
#define LL 1024
#define TT 64
#define DD 256
#define VV 30000
#define MEET 511   // forward covers t=0..511 (511 matvec steps), backward t=1023..512 (512 steps)

#define LN2f 0.6931471805599453f

// Vocab-level emission tables (L2-resident: 7.68 MB each)
__device__ float gEW[VV * TT];    // embed@W + b
__device__ float gExp[VV * TT];   // exp(embed@W + b)

// ---------------- packed f32x2 helpers ----------------
__device__ __forceinline__ unsigned long long fma2(unsigned long long a, unsigned long long b, unsigned long long c) {
    unsigned long long d;
    asm("fma.rn.f32x2 %0, %1, %2, %3;" : "=l"(d) : "l"(a), "l"(b), "l"(c));
    return d;
}
__device__ __forceinline__ unsigned long long add2(unsigned long long a, unsigned long long b) {
    unsigned long long d;
    asm("add.rn.f32x2 %0, %1, %2;" : "=l"(d) : "l"(a), "l"(b));
    return d;
}
__device__ __forceinline__ unsigned long long pack2(float lo, float hi) {
    unsigned long long d;
    asm("mov.b64 %0, {%1, %2};" : "=l"(d) : "f"(lo), "f"(hi));
    return d;
}
__device__ __forceinline__ float2 unpack2(unsigned long long v) {
    float lo, hi;
    asm("mov.b64 {%0, %1}, %2;" : "=f"(lo), "=f"(hi) : "l"(v));
    return make_float2(lo, hi);
}
__device__ __forceinline__ float frcp(float x) {
    float r;
    asm("rcp.approx.f32 %0, %1;" : "=r"(*(unsigned*)&r) : "r"(*(unsigned*)&x));
    return r;
}
__device__ __forceinline__ void named_bar(int id, int cnt) {
    asm volatile("bar.sync %0, %1;" :: "r"(id), "r"(cnt) : "memory");
}

// ---------------- Kernel A: EW = embed @ W + b over the VOCAB ----------------
#define ESTRIDE 68
#define SMEM_A_BYTES ((16384 + 128 * ESTRIDE) * 4)

__global__ void __launch_bounds__(256, 2)
emis_kernel(const float* __restrict__ embed, const float* __restrict__ W,
            const float* __restrict__ bias, float* __restrict__ out_scalar) {
    extern __shared__ float sm[];
    float* w_sh = sm;             // [256][64]
    float* e_sh = sm + 16384;     // [128][ESTRIDE]

    const int tid = threadIdx.x;
    if (blockIdx.x == 0 && tid == 0) *out_scalar = 0.0f;

    const int row_base = blockIdx.x * 128;

    {
        const float4* src = (const float4*)W;
        float4* dst = (float4*)w_sh;
        #pragma unroll
        for (int i = 0; i < 16; i++) dst[tid + 256 * i] = src[tid + 256 * i];
    }
    __syncthreads();

    const int lg = tid & 7;
    const int tg = tid >> 3;
    const int warp = tid >> 5, lane = tid & 31;

    unsigned long long acc[4][4];
    #pragma unroll
    for (int t = 0; t < 4; t++)
        #pragma unroll
        for (int q = 0; q < 4; q++) acc[t][q] = 0ull;

    for (int c = 0; c < 4; c++) {
        const int c0 = c * 64;
        #pragma unroll
        for (int pr = warp; pr < 64; pr += 8) {
            int tl = pr * 2 + (lane >> 4);
            int r = row_base + tl; if (r > VV - 1) r = VV - 1;
            int d4 = lane & 15;
            float4 v = *(const float4*)(embed + (size_t)r * DD + c0 + d4 * 4);
            *(float4*)&e_sh[tl * ESTRIDE + d4 * 4] = v;
        }
        __syncthreads();

        #pragma unroll 8
        for (int d = 0; d < 64; d++) {
            const ulonglong2* wrow = (const ulonglong2*)&w_sh[(c0 + d) * 64 + (lg << 3)];
            ulonglong2 w01 = wrow[0];
            ulonglong2 w23 = wrow[1];
            #pragma unroll
            for (int t = 0; t < 4; t++) {
                float e = e_sh[(tg * 4 + t) * ESTRIDE + d];
                unsigned long long e2 = pack2(e, e);
                acc[t][0] = fma2(e2, w01.x, acc[t][0]);
                acc[t][1] = fma2(e2, w01.y, acc[t][1]);
                acc[t][2] = fma2(e2, w23.x, acc[t][2]);
                acc[t][3] = fma2(e2, w23.y, acc[t][3]);
            }
        }
        __syncthreads();
    }

    float bb[8];
    #pragma unroll
    for (int k = 0; k < 8; k++) bb[k] = bias[(lg << 3) + k];

    #pragma unroll
    for (int t = 0; t < 4; t++) {
        int r = row_base + tg * 4 + t;
        if (r < VV) {
            float2 p0 = unpack2(acc[t][0]);
            float2 p1 = unpack2(acc[t][1]);
            float2 p2 = unpack2(acc[t][2]);
            float2 p3 = unpack2(acc[t][3]);
            float v[8] = { p0.x + bb[0], p0.y + bb[1], p1.x + bb[2], p1.y + bb[3],
                           p2.x + bb[4], p2.y + bb[5], p3.x + bb[6], p3.y + bb[7] };
            float4* ow = (float4*)(gEW + (size_t)r * TT + (lg << 3));
            ow[0] = make_float4(v[0], v[1], v[2], v[3]);
            ow[1] = make_float4(v[4], v[5], v[6], v[7]);
            float4* oe = (float4*)(gExp + (size_t)r * TT + (lg << 3));
            oe[0] = make_float4(__expf(v[0]), __expf(v[1]), __expf(v[2]), __expf(v[3]));
            oe[1] = make_float4(__expf(v[4]), __expf(v[5]), __expf(v[6]), __expf(v[7]));
        }
    }
}

// ---------------- Kernel B: CRF NLL, bidirectional linear-domain scan ----------------
// 128 CTAs x 256 threads.
//   warps 0-1  (tid   0..63 ): forward scan  (SMSP 0,1)
//   warps 4-5  (tid 128..191): backward scan (SMSP 0,1)  <- co-resident with forward
//   warps 2,3,6,7: gold-score partials in prologue, then exit.
// Normalization every 4th step only (scale tracked in C2 via log2(S)).
__global__ void __launch_bounds__(256)
crf_kernel(const int* __restrict__ x, const int* __restrict__ tags,
           const float* __restrict__ trans, float* __restrict__ out) {
    __shared__ float trans_sh[64 * 64];
    __shared__ __align__(16) float shpF[2][64];
    __shared__ __align__(16) float shpG[2][64];
    __shared__ float sF[64], sG[64];
    __shared__ float sgold[8];
    __shared__ float Cshare[2];
    __shared__ int sx[LL], stag[LL];

    const int tid = threadIdx.x;
    const int wid = tid >> 5, lane = tid & 31;
    const int b = blockIdx.x;
    const int base = b * LL;

    #pragma unroll
    for (int i = tid; i < 4096; i += 256) trans_sh[i] = trans[i];
    #pragma unroll
    for (int k = 0; k < 4; k++) {
        sx[tid + 256 * k]   = x[base + tid + 256 * k];
        stag[tid + 256 * k] = tags[base + tid + 256 * k];
    }
    __syncthreads();

    // Gold-path partials over all 256 threads (random L2 lookups, high MLP)
    {
        float gp = 0.0f;
        #pragma unroll
        for (int t = tid; t < LL; t += 256)
            gp += gEW[(size_t)sx[t] * TT + stag[t]];
        #pragma unroll
        for (int t = tid; t < LL - 1; t += 256)
            gp += trans_sh[stag[t] * 64 + stag[t + 1]];
        #pragma unroll
        for (int off = 16; off; off >>= 1)
            gp += __shfl_xor_sync(0xffffffffu, gp, off);
        if (lane == 0) sgold[wid] = gp;
    }
    __syncthreads();

    const bool is_fwd = (wid < 2);
    const bool is_bwd = (wid == 4 || wid == 5);
    if (!is_fwd && !is_bwd) return;   // helper warps done

    if (is_fwd) {
        // ===================== FORWARD (warps 0-1, SMSP 0/1) =====================
        const int j = tid;
        unsigned long long E2[32];   // E column j, source-pairs
        #pragma unroll
        for (int i = 0; i < 32; i++)
            E2[i] = pack2(__expf(trans_sh[(2 * i) * 64 + j]),
                          __expf(trans_sh[(2 * i + 1) * 64 + j]));
        const float Estart = __expf(trans_sh[j]);

        float p = gExp[(size_t)sx[0] * TT + j] * Estart;
        float Cf = 0.0f;

        float embuf[4];
        #pragma unroll
        for (int k = 1; k <= 4; k++) embuf[k & 3] = gExp[(size_t)sx[k] * TT + j];

        #pragma unroll 4
        for (int t = 1; t <= MEET; t++) {
            float expem = embuf[t & 3];
            if (t + 4 <= MEET) embuf[t & 3] = gExp[(size_t)sx[t + 4] * TT + j];

            shpF[t & 1][j] = p;
            named_bar(1, 64);

            const ulonglong2* sp = (const ulonglong2*)shpF[t & 1];
            unsigned long long aA = 0ull, aB = 0ull, aC = 0ull, aD = 0ull;
            if ((t & 3) == 0) {
                unsigned long long sacc = 0ull;
                #pragma unroll
                for (int q = 0; q < 16; q++) {
                    ulonglong2 u = sp[q];
                    if (q & 1) { aB = fma2(u.x, E2[2 * q], aB); aD = fma2(u.y, E2[2 * q + 1], aD); }
                    else       { aA = fma2(u.x, E2[2 * q], aA); aC = fma2(u.y, E2[2 * q + 1], aC); }
                    if (q == 4) sacc = add2(u.x, u.y);
                    if (q == 5) sacc = add2(sacc, add2(u.x, u.y));
                }
                float2 Sf = unpack2(sacc);
                float S = Sf.x + Sf.y;                 // subset sum (8 healthy labels) > 0
                float2 sf = unpack2(add2(add2(aA, aB), add2(aC, aD)));
                float s = sf.x + sf.y;
                float invS = frcp(S);
                Cf += __log2f(S);
                p = s * expem * invS;
            } else {
                #pragma unroll
                for (int q = 0; q < 16; q++) {
                    ulonglong2 u = sp[q];
                    if (q & 1) { aB = fma2(u.x, E2[2 * q], aB); aD = fma2(u.y, E2[2 * q + 1], aD); }
                    else       { aA = fma2(u.x, E2[2 * q], aA); aC = fma2(u.y, E2[2 * q + 1], aC); }
                }
                float2 sf = unpack2(add2(add2(aA, aB), add2(aC, aD)));
                p = (sf.x + sf.y) * expem;             // carry scale; bounded over <=4 steps
            }
        }
        sF[j] = p;                 // f_MEET, scale 2^Cf
        if (j == 0) Cshare[0] = Cf;
    } else {
        // ===================== BACKWARD (warps 4-5, SMSP 0/1) =====================
        const int i = tid - 128;
        unsigned long long E2r[32];  // E row i, dest-pairs
        #pragma unroll
        for (int k = 0; k < 32; k++)
            E2r[k] = pack2(__expf(trans_sh[i * 64 + 2 * k]),
                           __expf(trans_sh[i * 64 + 2 * k + 1]));

        float g = __expf(trans_sh[i * 64 + 1]);   // Eend(i)
        float Cb = 0.0f;

        float embuf[4];
        #pragma unroll
        for (int k = 0; k < 4; k++) embuf[(LL - 1 - k) & 3] = gExp[(size_t)sx[LL - 1 - k] * TT + i];

        #pragma unroll 4
        for (int t = LL - 1; t > MEET; t--) {
            float pe = embuf[t & 3];
            if (t - 4 > MEET) embuf[t & 3] = gExp[(size_t)sx[t - 4] * TT + i];

            shpG[t & 1][i] = pe * g;              // h_t(i)
            named_bar(2, 64);

            const ulonglong2* sp = (const ulonglong2*)shpG[t & 1];
            unsigned long long aA = 0ull, aB = 0ull, aC = 0ull, aD = 0ull;
            if ((t & 3) == 0) {
                unsigned long long sacc = 0ull;
                #pragma unroll
                for (int q = 0; q < 16; q++) {
                    ulonglong2 u = sp[q];
                    if (q & 1) { aB = fma2(u.x, E2r[2 * q], aB); aD = fma2(u.y, E2r[2 * q + 1], aD); }
                    else       { aA = fma2(u.x, E2r[2 * q], aA); aC = fma2(u.y, E2r[2 * q + 1], aC); }
                    if (q == 4) sacc = add2(u.x, u.y);
                    if (q == 5) sacc = add2(sacc, add2(u.x, u.y));
                }
                float2 Sf = unpack2(sacc);
                float S = Sf.x + Sf.y;
                float2 sf = unpack2(add2(add2(aA, aB), add2(aC, aD)));
                float s = sf.x + sf.y;
                float invS = frcp(S);
                Cb += __log2f(S);
                g = s * invS;
            } else {
                #pragma unroll
                for (int q = 0; q < 16; q++) {
                    ulonglong2 u = sp[q];
                    if (q & 1) { aB = fma2(u.x, E2r[2 * q], aB); aD = fma2(u.y, E2r[2 * q + 1], aD); }
                    else       { aA = fma2(u.x, E2r[2 * q], aA); aC = fma2(u.y, E2r[2 * q + 1], aC); }
                }
                float2 sf = unpack2(add2(add2(aA, aB), add2(aC, aD)));
                g = sf.x + sf.y;                  // carry scale
            }
        }
        sG[i] = g;                 // g_MEET, scale 2^Cb
        if (i == 0) Cshare[1] = Cb;
    }

    named_bar(3, 128);             // fwd + bwd groups only (helpers have exited)

    if (tid == 0) {
        float Z = 0.0f, gold = 0.0f;
        #pragma unroll 8
        for (int k = 0; k < 64; k++) Z += sF[k] * sG[k];
        #pragma unroll
        for (int k = 0; k < 8; k++) gold += sgold[k];
        float logz = LN2f * (Cshare[0] + Cshare[1] + __log2f(Z));
        float score = gold + trans_sh[stag[0]] + trans_sh[stag[LL - 1] * 64 + 1];
        atomicAdd(out, logz - score);   // out = -sum(scores - log_z)
    }
}

// ---------------- launch ----------------
extern "C" void kernel_launch(void* const* d_in, const int* in_sizes, int n_in,
                              void* d_out, int out_size) {
    const int*   x     = (const int*)d_in[0];
    const int*   tags  = (const int*)d_in[1];
    // d_in[2] = mask (ignored by reference CRF)
    const float* embed = (const float*)d_in[3];
    const float* W     = (const float*)d_in[4];
    const float* bias  = (const float*)d_in[5];
    const float* trans = (const float*)d_in[6];
    float* out = (float*)d_out;

    static bool attr_set = false;
    if (!attr_set) {
        cudaFuncSetAttribute(emis_kernel, cudaFuncAttributeMaxDynamicSharedMemorySize, SMEM_A_BYTES);
        attr_set = true;
    }

    emis_kernel<<<(VV + 127) / 128, 256, SMEM_A_BYTES>>>(embed, W, bias, out);
    crf_kernel<<<BB, 256>>>(x, tags, trans, out);
}